// round 15
// baseline (speedup 1.0000x reference)
#include <cuda_runtime.h>
#include <cuda_fp16.h>
#include <cstdint>

// ---------------------------------------------------------------------------
// Problem:
//   Ec : (128 chan, 256 s, 3 l, 128 d) f32
//   W1 : (6,128,128,1,128)  W2 : (5,128,128,2,128)  W3 : (5,128,128,3,128)
//   b1 : (6,128) b2 : (5,128) b3 : (5,128)
//   out: (128 o, 256 s, 1, 16 k) f32
// 33 conv maps: z<18 -> h=1 (kl=z/3, p=z%3); z<28 -> h=2; else h=3.
// GEMM per map: out[o,s] = sum_{a,c,d} Ec[a,s,p+c,d] * W[kl,o,a,c,d]
//   M=256(s), N=128(o), K=128*h*128.
// R14: eliminate the Ec fp16 pre-pass. 4 producer warps (not R11's 2 -> 2x
// the LDG bytes-in-flight, fixing the latency-throughput shortfall) feed
// BOTH A (Ec f32 -> fp16) and B (W f32 -> fp16) into a 2-stage smem ring.
// Consumers (warps 0-7) are pure ldmatrix + mma.sync f32-acc (rt=16/SMSP
// floor). Reduce = R13's single-pass (block=(o,k)). Two launches total.
// ---------------------------------------------------------------------------

#define NMAPS 33
#define SLOT_STRIDE 24            // max chunks per map = 8*h <= 24
__device__ float g_part[NMAPS * SLOT_STRIDE * 32768];   // split-K partials

#define PITCH 144                 // smem row pitch: 128B fp16 data + 16B pad
#define OFF_A 0                   // A: 256 rows (s)
#define OFF_B (256 * PITCH)       // B: 128 rows (o)
#define STAGE_BYTES (384 * PITCH) // 55296
#define NSTAGE 2
#define SMEM_BYTES (NSTAGE * STAGE_BYTES)      // 110592
#define NTHREADS 384              // 8 consumer warps + 4 producer warps
#define NST 32                    // k64 stages per K=2048 chunk

// ---------------------------------------------------------------------------
__device__ __forceinline__ uint32_t smem_u32(const void* p) {
    uint32_t r;
    asm("{ .reg .u64 t; cvta.to.shared.u64 t, %1; cvt.u32.u64 %0, t; }"
        : "=r"(r) : "l"(p));
    return r;
}

__device__ __forceinline__ void ldm4(uint32_t (&r)[4], uint32_t addr) {
    asm volatile("ldmatrix.sync.aligned.m8n8.x4.shared.b16 {%0,%1,%2,%3}, [%4];"
        : "=r"(r[0]), "=r"(r[1]), "=r"(r[2]), "=r"(r[3]) : "r"(addr));
}

__device__ __forceinline__ void mma_fp16(float (&d)[4], const uint32_t (&a)[4],
                                         uint32_t b0, uint32_t b1) {
    asm volatile(
        "mma.sync.aligned.m16n8k16.row.col.f32.f16.f16.f32 "
        "{%0,%1,%2,%3}, {%4,%5,%6,%7}, {%8,%9}, {%0,%1,%2,%3};"
        : "+f"(d[0]), "+f"(d[1]), "+f"(d[2]), "+f"(d[3])
        : "r"(a[0]), "r"(a[1]), "r"(a[2]), "r"(a[3]), "r"(b0), "r"(b1));
}

// f32x4 -> fp16x4 (8 bytes)
__device__ __forceinline__ uint2 cvt4(float4 v) {
    __half2 h01 = __floats2half2_rn(v.x, v.y);
    __half2 h23 = __floats2half2_rn(v.z, v.w);
    uint2 r;
    r.x = *reinterpret_cast<uint32_t*>(&h01);
    r.y = *reinterpret_cast<uint32_t*>(&h23);
    return r;
}

// ---------------------------------------------------------------------------
// GEMM: grid(424). One CTA = one map z, one K-chunk of 16 (a,c) pairs
// (K=2048), full M=256(s), full N=128(o). 32 stages of k64, 2-buffer ring.
// Consumers (warps 0-7): warp tile 64x64, pure ldmatrix + mma.
// Producers (warps 8-11): A+B feed, 4 rounds x 12 float4/thread, depth-2
// register pipeline (LDG f32 -> cvt fp16 -> STS).
// ---------------------------------------------------------------------------
__global__ __launch_bounds__(NTHREADS, 1)
void vrtconv_gemm(const float* __restrict__ Ec,
                  const float* __restrict__ W1, const float* __restrict__ W2,
                  const float* __restrict__ W3)
{
    extern __shared__ char smem[];
    const int tid  = threadIdx.x;
    const int lane = tid & 31;
    const int wid  = tid >> 5;
    const bool consumer = (wid < 8);
    const uint32_t sb = smem_u32(smem);

    // job decode: j -> (z, chunk, h)
    const int j = blockIdx.x;
    int z, chunk, h;
    if (j < 144)      { z = j >> 3;                  chunk = j & 7;    h = 1; }
    else if (j < 304) { int t = j - 144; z = 18 + (t >> 4); chunk = t & 15; h = 2; }
    else              { int t = j - 304; z = 28 + t / 24;   chunk = t % 24; h = 3; }

    int kl, p; const float* W;
    if (h == 1)      { kl = z / 3;         p = z % 3;        W = W1; }
    else if (h == 2) { kl = (z - 18) >> 1; p = (z - 18) & 1; W = W2; }
    else             { kl = z - 28;        p = 0;            W = W3; }

    const size_t oStride = (size_t)16384 * h;        // o-stride in W (f32)
    const float* Wk = W + (size_t)kl * 2097152 * (size_t)h;

    if (consumer) {
        // ---------------- consumer warps: pure MMA pipeline ----------------
        const int wm = wid & 3;      // 4 m-warps (64 s each)
        const int wn = wid >> 2;     // 2 n-warps (64 o each)

        float acc[4][8][4];
        #pragma unroll
        for (int a = 0; a < 4; ++a)
            #pragma unroll
            for (int b = 0; b < 8; ++b)
                #pragma unroll
                for (int c = 0; c < 4; ++c) acc[a][b][c] = 0.0f;

        const uint32_t aByte = (uint32_t)((wm * 64 + (lane & 15)) * PITCH
                                          + (lane >> 4) * 16);
        const uint32_t bByte = (uint32_t)((wn * 64 + (lane & 15)) * PITCH
                                          + (lane >> 4) * 16);

        for (int st = 0; st < NST; ++st) {
            __syncthreads();                       // stage st (A & B) ready

            const uint32_t bufb = sb + (uint32_t)((st & 1) * STAGE_BYTES);
            #pragma unroll
            for (int kk = 0; kk < 4; ++kk) {       // k64 = 4 x k16
                uint32_t af[4][4], bf[4][4];
                #pragma unroll
                for (int mt = 0; mt < 4; ++mt)
                    ldm4(af[mt], bufb + OFF_A + aByte + mt * (16 * PITCH) + kk * 32);
                #pragma unroll
                for (int nj = 0; nj < 4; ++nj)
                    ldm4(bf[nj], bufb + OFF_B + bByte + nj * (16 * PITCH) + kk * 32);
                #pragma unroll
                for (int mt = 0; mt < 4; ++mt)
                    #pragma unroll
                    for (int nj = 0; nj < 4; ++nj) {
                        mma_fp16(acc[mt][nj * 2],     af[mt], bf[nj][0], bf[nj][2]);
                        mma_fp16(acc[mt][nj * 2 + 1], af[mt], bf[nj][1], bf[nj][3]);
                    }
            }
        }

        // epilogue: partials [map][chunk][o:128][s:256]
        float* dst = g_part + ((size_t)z * SLOT_STRIDE + chunk) * 32768;
        #pragma unroll
        for (int mt = 0; mt < 4; ++mt) {
            const int s0 = wm * 64 + mt * 16 + (lane >> 2);
            #pragma unroll
            for (int n8 = 0; n8 < 8; ++n8) {
                const int o = wn * 64 + n8 * 8 + (lane & 3) * 2;
                dst[(size_t)o * 256 + s0]           = acc[mt][n8][0];
                dst[(size_t)(o + 1) * 256 + s0]     = acc[mt][n8][1];
                dst[(size_t)o * 256 + s0 + 8]       = acc[mt][n8][2];
                dst[(size_t)(o + 1) * 256 + s0 + 8] = acc[mt][n8][3];
            }
        }
    } else {
        // ------ producer warps (4): A (Ec f32) + B (W f32) -> fp16 smem ----
        const int ptid = tid - 256;               // 0..127
        // combined flat space: [0,4096) = A (256 rows x 16 f4),
        //                      [4096,6144) = B (128 rows x 16 f4)
        // 4 rounds x 12 f4/thread; boundary at round 2, i=8 (compile-time).
        float4 buf[2][12];

        auto produce = [&](int st) {
            const int q  = chunk * 16 + (st >> 1);
            const int d0 = (st & 1) * 64;
            int a, cl;
            if (h == 1)      { a = q;      cl = 0;     }
            else if (h == 2) { a = q >> 1; cl = q & 1; }
            else             { a = q / 3;  cl = q % 3; }
            const float* Asrc = Ec + (size_t)a * 98304
                              + (size_t)(p + cl) * 128 + d0;
            const float* Bsrc = Wk + (size_t)q * 128 + d0;
            char* base = smem + (st & 1) * STAGE_BYTES;

            #pragma unroll
            for (int r = 0; r <= 4; ++r) {
                if (r < 4) {                       // load round r
                    float4* bb = buf[r & 1];
                    #pragma unroll
                    for (int i = 0; i < 12; ++i) {
                        const int slot = r * 12 + i;        // compile-time
                        const int flat = slot * 128 + ptid;
                        if (slot < 32) {           // A region
                            const int row = flat >> 4, c4 = flat & 15;
                            bb[i] = *reinterpret_cast<const float4*>(
                                Asrc + (size_t)row * 384 + c4 * 4);
                        } else {                   // B region
                            const int f2 = flat - 4096;
                            const int row = f2 >> 4, c4 = f2 & 15;
                            bb[i] = *reinterpret_cast<const float4*>(
                                Bsrc + (size_t)row * oStride + c4 * 4);
                        }
                    }
                }
                if (r > 0) {                       // store round r-1
                    const int rp = r - 1;
                    float4* bb = buf[rp & 1];
                    #pragma unroll
                    for (int i = 0; i < 12; ++i) {
                        const int slot = rp * 12 + i;
                        const int flat = slot * 128 + ptid;
                        if (slot < 32) {
                            const int row = flat >> 4, c4 = flat & 15;
                            *reinterpret_cast<uint2*>(
                                base + OFF_A + row * PITCH + c4 * 8) = cvt4(bb[i]);
                        } else {
                            const int f2 = flat - 4096;
                            const int row = f2 >> 4, c4 = f2 & 15;
                            *reinterpret_cast<uint2*>(
                                base + OFF_B + row * PITCH + c4 * 8) = cvt4(bb[i]);
                        }
                    }
                }
            }
        };

        // prologue: stage 0 fully staged before first barrier
        produce(0);

        for (int st = 0; st < NST; ++st) {
            __syncthreads();                       // pairs with consumer barrier
            if (st + 1 < NST) produce(st + 1);
        }
    }
}

// ---------------------------------------------------------------------------
// Single-pass reduce: block = (o, k). 2048 blocks x 256 threads (thread = s).
// Each thread: sum 8h chunks for each of P maps, + bias, max, ReLU, store.
// ---------------------------------------------------------------------------
__global__ void vrtconv_reduce(const float* __restrict__ b1,
                               const float* __restrict__ b2,
                               const float* __restrict__ b3,
                               float* __restrict__ out)
{
    const int o = blockIdx.x >> 4;
    const int k = blockIdx.x & 15;
    const int s = threadIdx.x;

    const int h_idx = k % 3;       // k = h_idx + 3*jj
    const int jj    = k / 3;
    const int P     = 3 - h_idx;
    const int base  = (h_idx == 0) ? 0 : (h_idx == 1 ? 18 : 28);
    const int nch   = 8 * (h_idx + 1);
    const float* bb = (h_idx == 0) ? b1 : (h_idx == 1 ? b2 : b3);
    const float bias = bb[jj * 128 + o];

    float m = -1e30f;
    for (int pp = 0; pp < P; ++pp) {
        const int zmap = base + jj * P + pp;
        const float* q = g_part + (size_t)zmap * SLOT_STRIDE * 32768
                       + (size_t)o * 256 + s;
        float sum = 0.0f;
        #pragma unroll 8
        for (int cc = 0; cc < nch; ++cc) sum += q[(size_t)cc * 32768];
        m = fmaxf(m, sum + bias);
    }
    out[((size_t)o * 256 + s) * 16 + k] = fmaxf(m, 0.0f);
}

// ---------------------------------------------------------------------------
extern "C" void kernel_launch(void* const* d_in, const int* in_sizes, int n_in,
                              void* d_out, int out_size) {
    const float* Ec = (const float*)d_in[0];
    const float* W1 = (const float*)d_in[1];
    const float* W2 = (const float*)d_in[2];
    const float* W3 = (const float*)d_in[3];
    const float* b1 = (const float*)d_in[4];
    const float* b2 = (const float*)d_in[5];
    const float* b3 = (const float*)d_in[6];
    float* out = (float*)d_out;

    cudaFuncSetAttribute(vrtconv_gemm,
                         cudaFuncAttributeMaxDynamicSharedMemorySize, SMEM_BYTES);
    vrtconv_gemm<<<424, NTHREADS, SMEM_BYTES>>>(Ec, W1, W2, W3);

    vrtconv_reduce<<<2048, 256>>>(b1, b2, b3, out);
}